// round 7
// baseline (speedup 1.0000x reference)
#include <cuda_runtime.h>
#include <cstdint>

#define N_NODES 100000
#define N_EDGES 1600000
#define C 32
#define SLOTS 64   // P(Poisson(16) > 64) ~ 1e-20; guard keeps OOB-safe

// Scratch (device globals; zero-initialized at module load).
// g_cursor is reset to zero by k_gather each call -> replay-safe.
__device__ int   g_cursor[N_NODES];
__device__ int   g_elist[N_NODES * SLOTS];     // 25.6 MB bin storage
__device__ float g_dinv[N_NODES];
__device__ float g_hs[N_NODES * C];            // hs[i] = (x[i] @ W^T) * dinv[i]

// ---------------------------------------------------------------------------
// K1: bin edges by target; cursor doubles as in-degree histogram.
//     2 edges/thread, chains interleaved for MLP=2 on the ATOMG->STG path.
__global__ void k_fill(const int* __restrict__ rowv,
                       const int* __restrict__ colv) {
    int t = blockIdx.x * blockDim.x + threadIdx.x;
    int e0 = t * 2;
    if (e0 + 1 < N_EDGES) {
        int2 cc = *reinterpret_cast<const int2*>(colv + e0);
        int2 rr = *reinterpret_cast<const int2*>(rowv + e0);
        int p0 = atomicAdd(&g_cursor[cc.x], 1);
        int p1 = atomicAdd(&g_cursor[cc.y], 1);
        if (p0 < SLOTS) g_elist[cc.x * SLOTS + p0] = rr.x;
        if (p1 < SLOTS) g_elist[cc.y * SLOTS + p1] = rr.y;
    } else if (e0 < N_EDGES) {
        int c = __ldg(colv + e0);
        int r = __ldg(rowv + e0);
        int p = atomicAdd(&g_cursor[c], 1);
        if (p < SLOTS) g_elist[c * SLOTS + p] = r;
    }
}

// K2: dinv = rsqrt(deg+1); hs = (x @ W^T) * dinv.
//     Reads g_cursor as degree (gather resets it). Block = 8 nodes x 32 ch.
__global__ void k_gemm(const float* __restrict__ x,
                       const float* __restrict__ W) {
    __shared__ float Wsh[C][C + 1];   // Wsh[k][co] = W[co*C + k]
    int tid = threadIdx.x;
    #pragma unroll
    for (int i = tid; i < C * C; i += 256) {
        Wsh[i % C][i / C] = W[i];
    }
    __syncthreads();

    int n  = blockIdx.x * 8 + (tid >> 5);
    int co = tid & 31;
    if (n >= N_NODES) return;

    float dinv = rsqrtf((float)(g_cursor[n] + 1));   // +1 = self loop
    if (co == 0) g_dinv[n] = dinv;

    const float* xr = x + n * C;
    float acc = 0.0f;
    #pragma unroll
    for (int k = 0; k < C; k++) acc += __ldg(xr + k) * Wsh[k][co];

    g_hs[n * C + co] = acc * dinv;
}

// K3: atomic-free gather, warp per node, lane = channel.
//     Batch-load 32 edge indices coalesced, shfl-broadcast each; the ~deg
//     hs loads are mutually independent (MLP = deg) and 128B-coalesced.
//     out[n] = dinv[n]*(hs[n] + sum hs[src]) + b; resets cursor for replay.
__global__ void k_gather(float* __restrict__ out, const float* __restrict__ b) {
    int warp = blockIdx.x * 8 + (threadIdx.x >> 5);   // node id
    int lane = threadIdx.x & 31;
    if (warp >= N_NODES) return;
    int n = warp;

    int deg = g_cursor[n];            // broadcast load
    if (lane == 0) g_cursor[n] = 0;   // reset for next replay
    int cnt = min(deg, SLOTS);

    const int* el = g_elist + n * SLOTS;
    float acc = g_hs[n * C + lane];   // self-loop term

    for (int base = 0; base < cnt; base += 32) {
        int m = min(cnt - base, 32);
        int r = (lane < m) ? __ldg(el + base + lane) : 0;
        for (int j = 0; j < m; j++) {
            int rr = __shfl_sync(0xFFFFFFFFu, r, j);
            acc += __ldg(g_hs + rr * C + lane);
        }
    }

    out[n * C + lane] = fmaf(acc, g_dinv[n], __ldg(b + lane));
}

// ---------------------------------------------------------------------------
extern "C" void kernel_launch(void* const* d_in, const int* in_sizes, int n_in,
                              void* d_out, int out_size) {
    const float* x  = (const float*)d_in[0];
    const int*   ei = (const int*)d_in[1];    // [2, E]: row then col
    const float* W  = (const float*)d_in[2];
    const float* b  = (const float*)d_in[3];
    float* out = (float*)d_out;

    const int* rowv = ei;
    const int* colv = ei + N_EDGES;

    k_fill<<<(N_EDGES / 2 + 255) / 256, 256>>>(rowv, colv);
    k_gemm<<<(N_NODES + 7) / 8, 256>>>(x, W);
    k_gather<<<(N_NODES + 7) / 8, 256>>>(out, b);
}

// round 8
// speedup vs baseline: 2.2754x; 2.2754x over previous
#include <cuda_runtime.h>
#include <cstdint>

#define N_NODES 100000
#define N_EDGES 1600000
#define C 32
#define SLOTS 64   // P(Poisson(16) > 64) ~ 1e-20; guard keeps OOB-safe

// Scratch (device globals; zero-initialized at module load).
// g_cursor is reset to zero by k_gather each call -> replay-safe.
__device__ int    g_cursor[N_NODES];
__device__ int    g_elist[N_NODES * SLOTS];     // 25.6 MB bin storage
__device__ float  g_dinv[N_NODES];
__device__ float4 g_hs[N_NODES * (C / 4)];      // hs[i] = (x[i] @ W^T) * dinv[i]

// ---------------------------------------------------------------------------
// K1: bin edges by target; cursor doubles as in-degree histogram.
//     (At the LTS atomic-ALU floor ~20us; keep simple.)
__global__ void k_fill(const int* __restrict__ rowv,
                       const int* __restrict__ colv) {
    int e = blockIdx.x * blockDim.x + threadIdx.x;
    if (e < N_EDGES) {
        int c = __ldg(colv + e);
        int r = __ldg(rowv + e);
        int pos = atomicAdd(&g_cursor[c], 1);
        if (pos < SLOTS) g_elist[c * SLOTS + pos] = r;
    }
}

// K2: dinv = rsqrt(deg+1); hs = (x @ W^T) * dinv.
//     Reads g_cursor as degree (gather resets it). Block = 8 nodes x 32 ch.
__global__ void k_gemm(const float* __restrict__ x,
                       const float* __restrict__ W) {
    __shared__ float Wsh[C][C + 1];   // Wsh[k][co] = W[co*C + k]
    int tid = threadIdx.x;
    #pragma unroll
    for (int i = tid; i < C * C; i += 256) {
        Wsh[i % C][i / C] = W[i];
    }
    __syncthreads();

    int n  = blockIdx.x * 8 + (tid >> 5);
    int co = tid & 31;
    if (n >= N_NODES) return;

    float dinv = rsqrtf((float)(g_cursor[n] + 1));   // +1 = self loop
    if (co == 0) g_dinv[n] = dinv;

    const float* xr = x + n * C;
    float acc = 0.0f;
    #pragma unroll
    for (int k = 0; k < C; k++) acc += __ldg(xr + k) * Wsh[k][co];

    reinterpret_cast<float*>(g_hs)[n * C + co] = acc * dinv;
}

// K3: atomic-free gather. 8 lanes per node, lane g owns float4 channel
//     group g. Per 16-edge round: 4 independent int4 index loads, then 16
//     independent float4 hs loads (MLP=16), then accumulate.
//     out[n] = dinv[n]*(hs[n] + sum hs[src]) + b; resets cursor for replay.
__global__ void k_gather(float4* __restrict__ out, const float* __restrict__ b) {
    int t = blockIdx.x * blockDim.x + threadIdx.x;
    int n = t >> 3;
    int g = t & 7;
    if (n >= N_NODES) return;

    int deg = g_cursor[n];          // 8-lane broadcast load
    if (g == 0) g_cursor[n] = 0;    // reset for next replay
    int cnt = min(deg, SLOTS);

    const int4* el4 = reinterpret_cast<const int4*>(g_elist + n * SLOTS);
    float4 acc = g_hs[n * 8 + g];   // self-loop term

    int i = 0;
    // 16-edge rounds: max MLP
    for (; i + 16 <= cnt; i += 16) {
        int4 a0 = __ldg(el4 + (i >> 2));
        int4 a1 = __ldg(el4 + (i >> 2) + 1);
        int4 a2 = __ldg(el4 + (i >> 2) + 2);
        int4 a3 = __ldg(el4 + (i >> 2) + 3);
        float4 v0  = g_hs[a0.x * 8 + g];
        float4 v1  = g_hs[a0.y * 8 + g];
        float4 v2  = g_hs[a0.z * 8 + g];
        float4 v3  = g_hs[a0.w * 8 + g];
        float4 v4  = g_hs[a1.x * 8 + g];
        float4 v5  = g_hs[a1.y * 8 + g];
        float4 v6  = g_hs[a1.z * 8 + g];
        float4 v7  = g_hs[a1.w * 8 + g];
        float4 v8  = g_hs[a2.x * 8 + g];
        float4 v9  = g_hs[a2.y * 8 + g];
        float4 v10 = g_hs[a2.z * 8 + g];
        float4 v11 = g_hs[a2.w * 8 + g];
        float4 v12 = g_hs[a3.x * 8 + g];
        float4 v13 = g_hs[a3.y * 8 + g];
        float4 v14 = g_hs[a3.z * 8 + g];
        float4 v15 = g_hs[a3.w * 8 + g];
        acc.x += v0.x + v1.x + v2.x + v3.x + v4.x + v5.x + v6.x + v7.x
               + v8.x + v9.x + v10.x + v11.x + v12.x + v13.x + v14.x + v15.x;
        acc.y += v0.y + v1.y + v2.y + v3.y + v4.y + v5.y + v6.y + v7.y
               + v8.y + v9.y + v10.y + v11.y + v12.y + v13.y + v14.y + v15.y;
        acc.z += v0.z + v1.z + v2.z + v3.z + v4.z + v5.z + v6.z + v7.z
               + v8.z + v9.z + v10.z + v11.z + v12.z + v13.z + v14.z + v15.z;
        acc.w += v0.w + v1.w + v2.w + v3.w + v4.w + v5.w + v6.w + v7.w
               + v8.w + v9.w + v10.w + v11.w + v12.w + v13.w + v14.w + v15.w;
    }
    // 4-edge rounds
    for (; i + 4 <= cnt; i += 4) {
        int4 a = __ldg(el4 + (i >> 2));
        float4 v0 = g_hs[a.x * 8 + g];
        float4 v1 = g_hs[a.y * 8 + g];
        float4 v2 = g_hs[a.z * 8 + g];
        float4 v3 = g_hs[a.w * 8 + g];
        acc.x += v0.x + v1.x + v2.x + v3.x;
        acc.y += v0.y + v1.y + v2.y + v3.y;
        acc.z += v0.z + v1.z + v2.z + v3.z;
        acc.w += v0.w + v1.w + v2.w + v3.w;
    }
    // tail
    const int* el = g_elist + n * SLOTS;
    for (; i < cnt; i++) {
        int r = __ldg(el + i);
        float4 v = g_hs[r * 8 + g];
        acc.x += v.x; acc.y += v.y; acc.z += v.z; acc.w += v.w;
    }

    float d = g_dinv[n];
    float4 bb = *reinterpret_cast<const float4*>(b + g * 4);
    float4 o;
    o.x = fmaf(acc.x, d, bb.x);
    o.y = fmaf(acc.y, d, bb.y);
    o.z = fmaf(acc.z, d, bb.z);
    o.w = fmaf(acc.w, d, bb.w);
    out[n * 8 + g] = o;
}

// ---------------------------------------------------------------------------
extern "C" void kernel_launch(void* const* d_in, const int* in_sizes, int n_in,
                              void* d_out, int out_size) {
    const float* x  = (const float*)d_in[0];
    const int*   ei = (const int*)d_in[1];    // [2, E]: row then col
    const float* W  = (const float*)d_in[2];
    const float* b  = (const float*)d_in[3];
    float4* out = (float4*)d_out;

    const int* rowv = ei;
    const int* colv = ei + N_EDGES;

    k_fill<<<(N_EDGES + 255) / 256, 256>>>(rowv, colv);
    k_gemm<<<(N_NODES + 7) / 8, 256>>>(x, W);
    k_gather<<<(N_NODES * 8 + 255) / 256, 256>>>(out, b);
}